// round 2
// baseline (speedup 1.0000x reference)
#include <cuda_runtime.h>
#include <cstdint>

// Problem constants
#define Hdim   64
#define Wdim   64
#define HW     4096          // 64*64
#define CIN    256
#define COUT   256
#define BATCH  4
#define KK     9             // 3x3 taps
#define PDIM   (CIN * KK)    // 2304, GEMM K dimension

// Scratch (static device globals; no allocation anywhere)
__device__ float g_off[BATCH * 18 * HW];                 // offsets conv output (B,18,H,W)
__device__ float g_val[(size_t)BATCH * PDIM * HW];       // bilinear-sampled matrix (B, C*9, HW) ~151MB

// ---------------------------------------------------------------------------
// Kernel 1: offsets = conv2d(x, w_off), 3x3, pad 1, stride 1.
// One thread per (b, oc, ho, wo); wo fastest -> coalesced x reads & writes.
// ---------------------------------------------------------------------------
__global__ __launch_bounds__(256) void offsets_kernel(
    const float* __restrict__ x, const float* __restrict__ w_off)
{
    int idx = blockIdx.x * blockDim.x + threadIdx.x;
    if (idx >= BATCH * 18 * HW) return;
    int wo = idx & 63;
    int ho = (idx >> 6) & 63;
    int oc = (idx >> 12) % 18;
    int b  = idx / (18 * HW);

    const float* wp = w_off + oc * CIN * KK;
    const float* xb = x + (size_t)b * CIN * HW;

    float acc = 0.f;
    for (int c = 0; c < CIN; c++) {
        const float* xc = xb + c * HW;
        const float* wc = wp + c * KK;
#pragma unroll
        for (int ky = 0; ky < 3; ky++) {
            int y = ho + ky - 1;
            if (y < 0 || y >= Hdim) continue;   // uniform across warp (same ho)
            const float* xr = xc + y * Wdim;
#pragma unroll
            for (int kx = 0; kx < 3; kx++) {
                int xx = wo + kx - 1;
                float xv = (xx >= 0 && xx < Wdim) ? __ldg(xr + xx) : 0.f;
                acc += xv * __ldg(wc + ky * 3 + kx);
            }
        }
    }
    g_off[idx] = acc;
}

// ---------------------------------------------------------------------------
// Kernel 2: bilinear gather -> g_val[b][c*9+k][hw].
// One thread per (b, k, hw). Corner indices/weights computed ONCE, reused
// over all 256 channels (they don't depend on c).
// ---------------------------------------------------------------------------
__global__ __launch_bounds__(256) void gather_kernel(const float* __restrict__ x)
{
    int idx = blockIdx.x * blockDim.x + threadIdx.x;
    if (idx >= BATCH * KK * HW) return;
    int hw = idx & 4095;
    int k  = (idx >> 12) % KK;
    int b  = idx / (KK * HW);
    int ho = hw >> 6, wo = hw & 63;
    int ky = k / 3,  kx = k % 3;

    const float* offb = g_off + (size_t)b * 18 * HW;
    float dy = offb[(2 * k + 0) * HW + hw];
    float dx = offb[(2 * k + 1) * HW + hw];

    float py = (float)(ho - 1 + ky) + dy;
    float px = (float)(wo - 1 + kx) + dx;
    float y0f = floorf(py), x0f = floorf(px);
    int   y0 = (int)y0f,    x0 = (int)x0f;
    float wy1 = py - y0f, wx1 = px - x0f;
    float wy0 = 1.f - wy1, wx0 = 1.f - wx1;
    int y1 = y0 + 1, x1 = x0 + 1;

    bool vy0 = (y0 >= 0) & (y0 < Hdim);
    bool vy1 = (y1 >= 0) & (y1 < Hdim);
    bool vx0 = (x0 >= 0) & (x0 < Wdim);
    bool vx1 = (x1 >= 0) & (x1 < Wdim);

    float w00 = (vy0 && vx0) ? wy0 * wx0 : 0.f;
    float w01 = (vy0 && vx1) ? wy0 * wx1 : 0.f;
    float w10 = (vy1 && vx0) ? wy1 * wx0 : 0.f;
    float w11 = (vy1 && vx1) ? wy1 * wx1 : 0.f;

    int y0c = min(max(y0, 0), Hdim - 1), y1c = min(max(y1, 0), Hdim - 1);
    int x0c = min(max(x0, 0), Wdim - 1), x1c = min(max(x1, 0), Wdim - 1);
    int i00 = y0c * Wdim + x0c, i01 = y0c * Wdim + x1c;
    int i10 = y1c * Wdim + x0c, i11 = y1c * Wdim + x1c;

    const float* xb = x + (size_t)b * CIN * HW;
    float* vout = g_val + ((size_t)b * PDIM + k) * HW + hw;   // p = c*9 + k

    for (int c = 0; c < CIN; c++) {
        const float* xc = xb + c * HW;
        float v = w00 * __ldg(xc + i00) + w01 * __ldg(xc + i01)
                + w10 * __ldg(xc + i10) + w11 * __ldg(xc + i11);
        vout[(size_t)c * KK * HW] = v;
    }
}

// ---------------------------------------------------------------------------
// Kernel 3: SGEMM  C[b] = A[256,2304] * Bv[b][2304,4096]
// 128x128x8 tiles, 256 threads, 8x8 register microtile, float4 everywhere.
// Global->register prefetch double buffering hides LDG latency behind FFMAs.
// All dims divide the tile sizes exactly -> no bounds checks.
// ---------------------------------------------------------------------------
__global__ __launch_bounds__(256) void sgemm_kernel(
    const float* __restrict__ A, float* __restrict__ C)
{
    const int b = blockIdx.z;
    const float* Bp = g_val + (size_t)b * PDIM * HW;
    float*       Cp = C     + (size_t)b * COUT * HW;
    const int m0 = blockIdx.y * 128;
    const int n0 = blockIdx.x * 128;

    __shared__ float As[8][128];   // transposed: As[k][m]
    __shared__ float Bs[8][128];   // Bs[k][n]

    float acc[8][8];
#pragma unroll
    for (int i = 0; i < 8; i++)
#pragma unroll
        for (int j = 0; j < 8; j++) acc[i][j] = 0.f;

    const int tid   = threadIdx.x;
    const int arow  = tid >> 1;          // 0..127
    const int acol4 = (tid & 1) << 2;    // 0 or 4
    const int brow  = tid >> 5;          // 0..7
    const int bcol4 = (tid & 31) << 2;   // 0..124
    const int tx    = (tid & 15) << 3;   // 0..120 (N dir)
    const int ty    = (tid >> 4) << 3;   // 0..120 (M dir)

    const float* aptr = A  + (size_t)(m0 + arow) * PDIM + acol4;
    const float* bptr = Bp + (size_t)brow * HW + n0 + bcol4;

    // Prologue: load first K-tile fragments
    float4 a4 = *(const float4*)(aptr);
    float4 b4 = *(const float4*)(bptr);

    for (int kt = 0; kt < PDIM; kt += 8) {
        // Commit current fragments to shared
        As[acol4 + 0][arow] = a4.x;
        As[acol4 + 1][arow] = a4.y;
        As[acol4 + 2][arow] = a4.z;
        As[acol4 + 3][arow] = a4.w;
        *(float4*)&Bs[brow][bcol4] = b4;
        __syncthreads();

        // Prefetch next K-tile fragments (overlaps with FFMA block below)
        if (kt + 8 < PDIM) {
            a4 = *(const float4*)(aptr + kt + 8);
            b4 = *(const float4*)(bptr + (size_t)(kt + 8) * HW);
        }

#pragma unroll
        for (int kk = 0; kk < 8; kk++) {
            float ar[8], br[8];
            *(float4*)(ar + 0) = *(const float4*)&As[kk][ty];
            *(float4*)(ar + 4) = *(const float4*)&As[kk][ty + 4];
            *(float4*)(br + 0) = *(const float4*)&Bs[kk][tx];
            *(float4*)(br + 4) = *(const float4*)&Bs[kk][tx + 4];
#pragma unroll
            for (int i = 0; i < 8; i++)
#pragma unroll
                for (int j = 0; j < 8; j++)
                    acc[i][j] += ar[i] * br[j];
        }
        __syncthreads();
    }

#pragma unroll
    for (int i = 0; i < 8; i++) {
        float4 v0 = make_float4(acc[i][0], acc[i][1], acc[i][2], acc[i][3]);
        float4 v1 = make_float4(acc[i][4], acc[i][5], acc[i][6], acc[i][7]);
        float* crow = Cp + (size_t)(m0 + ty + i) * HW + n0 + tx;
        *(float4*)(crow + 0) = v0;
        *(float4*)(crow + 4) = v1;
    }
}

// ---------------------------------------------------------------------------
extern "C" void kernel_launch(void* const* d_in, const int* in_sizes, int n_in,
                              void* d_out, int out_size)
{
    const float* x     = (const float*)d_in[0];   // (4,256,64,64)
    const float* w_def = (const float*)d_in[1];   // (256,256,3,3)
    const float* w_off = (const float*)d_in[2];   // (18,256,3,3)
    float* out = (float*)d_out;                   // (4,256,64,64)

    offsets_kernel<<<(BATCH * 18 * HW + 255) / 256, 256>>>(x, w_off);
    gather_kernel<<<(BATCH * KK * HW + 255) / 256, 256>>>(x);
    sgemm_kernel<<<dim3(HW / 128, COUT / 128, BATCH), 256>>>(w_def, out);
}

// round 3
// speedup vs baseline: 1.4159x; 1.4159x over previous
#include <cuda_runtime.h>
#include <cstdint>

// Problem constants
#define Hdim   64
#define Wdim   64
#define HW     4096          // 64*64
#define CIN    256
#define COUT   256
#define BATCH  4
#define KK     9             // 3x3 taps
#define PDIM   (CIN * KK)    // 2304, GEMM K dimension

// Scratch (static device globals; no allocation anywhere)
__device__ float g_off[BATCH * 18 * HW];                 // offsets conv output (B,18,H,W)
__device__ float g_val[(size_t)BATCH * PDIM * HW];       // bilinear-sampled matrix (B, C*9, HW)

// ---------------------------------------------------------------------------
// Kernel 1: offsets = conv2d(x, w_off), 3x3, pad 1, stride 1.
// One thread per (b, ho, wo) pixel computing ALL 18 output channels.
// x stencil (9 values) loaded once per input channel into registers and
// reused across the 18 oc accumulators. Weights staged in smem transposed
// to ws[c][tap][oc] so the inner loop reads them as broadcast LDS.128.
// Block = 128 threads (2 rows of one image), grid = 4 * 32 = 128 blocks.
// ---------------------------------------------------------------------------
__global__ __launch_bounds__(128) void offsets_kernel(
    const float* __restrict__ x, const float* __restrict__ w_off)
{
    __shared__ float ws[8][9][20];   // [c][tap][oc] padded

    const int blk  = blockIdx.x;       // 0..127
    const int b    = blk >> 5;         // image
    const int row2 = (blk & 31) * 2;   // first of 2 rows
    const int ho   = row2 + (threadIdx.x >> 6);
    const int wo   = threadIdx.x & 63;

    float acc[18];
#pragma unroll
    for (int o = 0; o < 18; o++) acc[o] = 0.f;

    const float* xb = x + (size_t)b * CIN * HW;

    for (int c0 = 0; c0 < CIN; c0 += 8) {
        __syncthreads();
        for (int i = threadIdx.x; i < 18 * 8 * 9; i += 128) {
            int oc = i / 72; int rem = i % 72; int c = rem / 9; int tap = rem % 9;
            ws[c][tap][oc] = w_off[(size_t)oc * CIN * 9 + (size_t)(c0 + c) * 9 + tap];
        }
        __syncthreads();
#pragma unroll
        for (int c = 0; c < 8; c++) {
            const float* xc = xb + (size_t)(c0 + c) * HW;
            float xv[9];
#pragma unroll
            for (int ky = 0; ky < 3; ky++) {
                int y = ho + ky - 1;
                bool vy = (y >= 0) && (y < Hdim);
#pragma unroll
                for (int kx = 0; kx < 3; kx++) {
                    int xx = wo + kx - 1;
                    xv[ky * 3 + kx] = (vy && xx >= 0 && xx < Wdim) ? __ldg(xc + y * Wdim + xx) : 0.f;
                }
            }
#pragma unroll
            for (int tap = 0; tap < 9; tap++) {
                float xt = xv[tap];
#pragma unroll
                for (int o = 0; o < 18; o++)
                    acc[o] += xt * ws[c][tap][o];
            }
        }
    }

    const int hw = ho * Wdim + wo;
#pragma unroll
    for (int o = 0; o < 18; o++)
        g_off[((size_t)b * 18 + o) * HW + hw] = acc[o];
}

// ---------------------------------------------------------------------------
// Kernel 2: bilinear gather -> g_val[b][c*9+k][hw]. (unchanged)
// ---------------------------------------------------------------------------
__global__ __launch_bounds__(256) void gather_kernel(const float* __restrict__ x)
{
    int idx = blockIdx.x * blockDim.x + threadIdx.x;
    if (idx >= BATCH * KK * HW) return;
    int hw = idx & 4095;
    int k  = (idx >> 12) % KK;
    int b  = idx / (KK * HW);
    int ho = hw >> 6, wo = hw & 63;
    int ky = k / 3,  kx = k % 3;

    const float* offb = g_off + (size_t)b * 18 * HW;
    float dy = offb[(2 * k + 0) * HW + hw];
    float dx = offb[(2 * k + 1) * HW + hw];

    float py = (float)(ho - 1 + ky) + dy;
    float px = (float)(wo - 1 + kx) + dx;
    float y0f = floorf(py), x0f = floorf(px);
    int   y0 = (int)y0f,    x0 = (int)x0f;
    float wy1 = py - y0f, wx1 = px - x0f;
    float wy0 = 1.f - wy1, wx0 = 1.f - wx1;
    int y1 = y0 + 1, x1 = x0 + 1;

    bool vy0 = (y0 >= 0) & (y0 < Hdim);
    bool vy1 = (y1 >= 0) & (y1 < Hdim);
    bool vx0 = (x0 >= 0) & (x0 < Wdim);
    bool vx1 = (x1 >= 0) & (x1 < Wdim);

    float w00 = (vy0 && vx0) ? wy0 * wx0 : 0.f;
    float w01 = (vy0 && vx1) ? wy0 * wx1 : 0.f;
    float w10 = (vy1 && vx0) ? wy1 * wx0 : 0.f;
    float w11 = (vy1 && vx1) ? wy1 * wx1 : 0.f;

    int y0c = min(max(y0, 0), Hdim - 1), y1c = min(max(y1, 0), Hdim - 1);
    int x0c = min(max(x0, 0), Wdim - 1), x1c = min(max(x1, 0), Wdim - 1);
    int i00 = y0c * Wdim + x0c, i01 = y0c * Wdim + x1c;
    int i10 = y1c * Wdim + x0c, i11 = y1c * Wdim + x1c;

    const float* xb = x + (size_t)b * CIN * HW;
    float* vout = g_val + ((size_t)b * PDIM + k) * HW + hw;   // p = c*9 + k

    for (int c = 0; c < CIN; c++) {
        const float* xc = xb + c * HW;
        float v = w00 * __ldg(xc + i00) + w01 * __ldg(xc + i01)
                + w10 * __ldg(xc + i10) + w11 * __ldg(xc + i11);
        vout[(size_t)c * KK * HW] = v;
    }
}

// ---------------------------------------------------------------------------
// Kernel 3: TF32 tensor-core GEMM  C[b] = A[256,2304] * Bv[b][2304,4096]
// mma.sync.aligned.m16n8k8.row.col.f32.tf32.tf32.f32
// Block tile 128x128, BK=16, 256 threads (8 warps in 2x4 M*N layout),
// each warp computes 64x32 via 4x4 m16n8 mma tiles.
// Smem stores the k dim PERMUTED within each 8-group ({t, t+4} adjacent)
// so fragment loads are single LDS.64 ops.
// ---------------------------------------------------------------------------
#define BM 128
#define BN 128
#define BK 16
#define KPAD 18   // padded floats per smem row

__device__ __forceinline__ float f2tf32(float f) {
    unsigned r;
    asm("cvt.rna.tf32.f32 %0, %1;" : "=r"(r) : "f"(f));
    return __uint_as_float(r);
}

__device__ __forceinline__ void mma_tf32(float4& d, float2 alo, float2 ahi, float2 bb) {
    asm volatile(
        "mma.sync.aligned.m16n8k8.row.col.f32.tf32.tf32.f32 "
        "{%0,%1,%2,%3}, {%4,%5,%6,%7}, {%8,%9}, {%0,%1,%2,%3};"
        : "+f"(d.x), "+f"(d.y), "+f"(d.z), "+f"(d.w)
        : "r"(__float_as_uint(alo.x)), "r"(__float_as_uint(ahi.x)),
          "r"(__float_as_uint(alo.y)), "r"(__float_as_uint(ahi.y)),
          "r"(__float_as_uint(bb.x)),  "r"(__float_as_uint(bb.y)));
}

__global__ __launch_bounds__(256) void mma_gemm_kernel(
    const float* __restrict__ A, float* __restrict__ C)
{
    __shared__ float As[2][BM][KPAD];
    __shared__ float Bs[2][BN][KPAD];

    const int b  = blockIdx.z;
    const float* Bp = g_val + (size_t)b * PDIM * HW;
    float*       Cp = C     + (size_t)b * COUT * HW;
    const int m0 = blockIdx.y * BM;
    const int n0 = blockIdx.x * BN;

    const int tid  = threadIdx.x;
    const int warp = tid >> 5;
    const int lane = tid & 31;
    const int g = lane >> 2;            // 0..7
    const int t = lane & 3;             // 0..3
    const int wm = (warp >> 2) * 64;    // warp M offset: 0 or 64
    const int wn = (warp & 3) * 32;     // warp N offset: 0..96

    float4 acc[4][4];
#pragma unroll
    for (int i = 0; i < 4; i++)
#pragma unroll
        for (int j = 0; j < 4; j++) acc[i][j] = make_float4(0.f, 0.f, 0.f, 0.f);

    // gmem load mapping
    const int am = tid >> 1;                 // A row within tile, 0..127
    const int aq = (tid & 1) * 2;            // first of 2 quads (k4 index)
    const float* aptr = A + (size_t)(m0 + am) * PDIM + aq * 4;
    const int bk = tid >> 4;                 // B k-row within tile, 0..15
    const int bn = (tid & 15) * 4;           // B n offset, 0..60
    const float* bptr = Bp + (size_t)bk * HW + n0 + bn;

    // physical (permuted) k column for B row bk: pairs {t, t+4} adjacent
    const int bphys = 8 * (bk >> 3) + 2 * (bk & 3) + ((bk >> 2) & 1);

    float4 pa[2], pb[2];

    // prologue: load tile 0
    pa[0] = *(const float4*)(aptr);
    pa[1] = *(const float4*)(aptr + 4);
    pb[0] = *(const float4*)(bptr);
    pb[1] = *(const float4*)(bptr + 64);

    const int nk = PDIM / BK;   // 144
    for (int it = 0; it < nk; it++) {
        const int s = it & 1;

        // commit current tile to smem stage s (tf32-rounded, k-permuted)
#pragma unroll
        for (int j = 0; j < 2; j++) {
            const int q = aq + j;
            const int base = 8 * (q >> 1) + (q & 1);
            float4 v = pa[j];
            As[s][am][base + 0] = f2tf32(v.x);
            As[s][am][base + 2] = f2tf32(v.y);
            As[s][am][base + 4] = f2tf32(v.z);
            As[s][am][base + 6] = f2tf32(v.w);
        }
#pragma unroll
        for (int j = 0; j < 2; j++) {
            const int n = bn + 64 * j;
            float4 v = pb[j];
            Bs[s][n + 0][bphys] = f2tf32(v.x);
            Bs[s][n + 1][bphys] = f2tf32(v.y);
            Bs[s][n + 2][bphys] = f2tf32(v.z);
            Bs[s][n + 3][bphys] = f2tf32(v.w);
        }
        __syncthreads();

        // prefetch next tile while computing
        if (it + 1 < nk) {
            const int kt = (it + 1) * BK;
            pa[0] = *(const float4*)(aptr + kt);
            pa[1] = *(const float4*)(aptr + kt + 4);
            pb[0] = *(const float4*)(bptr + (size_t)kt * HW);
            pb[1] = *(const float4*)(bptr + (size_t)kt * HW + 64);
        }

        // compute 2 k8-steps from stage s
#pragma unroll
        for (int k8 = 0; k8 < 2; k8++) {
            const int cb = k8 * 8 + 2 * t;
            float2 alo[4], ahi[4], bb[4];
#pragma unroll
            for (int mt = 0; mt < 4; mt++) {
                alo[mt] = *(const float2*)&As[s][wm + mt * 16 + g][cb];
                ahi[mt] = *(const float2*)&As[s][wm + mt * 16 + g + 8][cb];
            }
#pragma unroll
            for (int nt = 0; nt < 4; nt++)
                bb[nt] = *(const float2*)&Bs[s][wn + nt * 8 + g][cb];
#pragma unroll
            for (int mt = 0; mt < 4; mt++)
#pragma unroll
                for (int nt = 0; nt < 4; nt++)
                    mma_tf32(acc[mt][nt], alo[mt], ahi[mt], bb[nt]);
        }
        __syncthreads();
    }

    // epilogue: D fragment -> gmem (c0,c1 at row g col 2t; c2,c3 at row g+8)
#pragma unroll
    for (int mt = 0; mt < 4; mt++) {
#pragma unroll
        for (int nt = 0; nt < 4; nt++) {
            const int row = m0 + wm + mt * 16 + g;
            const int col = n0 + wn + nt * 8 + 2 * t;
            float4 d = acc[mt][nt];
            *(float2*)(Cp + (size_t)row * HW + col)       = make_float2(d.x, d.y);
            *(float2*)(Cp + (size_t)(row + 8) * HW + col) = make_float2(d.z, d.w);
        }
    }
}

// ---------------------------------------------------------------------------
extern "C" void kernel_launch(void* const* d_in, const int* in_sizes, int n_in,
                              void* d_out, int out_size)
{
    const float* x     = (const float*)d_in[0];   // (4,256,64,64)
    const float* w_def = (const float*)d_in[1];   // (256,256,3,3)
    const float* w_off = (const float*)d_in[2];   // (18,256,3,3)
    float* out = (float*)d_out;                   // (4,256,64,64)

    offsets_kernel<<<BATCH * 32, 128>>>(x, w_off);
    gather_kernel<<<(BATCH * KK * HW + 255) / 256, 256>>>(x);
    mma_gemm_kernel<<<dim3(HW / BN, COUT / BM, BATCH), 256>>>(w_def, out);
}

// round 4
// speedup vs baseline: 2.0436x; 1.4433x over previous
#include <cuda_runtime.h>
#include <cstdint>

// Problem constants
#define Hdim   64
#define Wdim   64
#define HW     4096          // 64*64
#define CIN    256
#define COUT   256
#define BATCH  4
#define KK     9             // 3x3 taps
#define PDIM   (CIN * KK)    // 2304, GEMM K dimension
#define NSPLIT 8             // channel splits for offsets conv

// Scratch (static device globals; no allocation anywhere)
__device__ float g_offp[NSPLIT][BATCH * 18 * HW];        // partial offsets (per channel split)
__device__ float g_val[(size_t)BATCH * PDIM * HW];       // bilinear-sampled matrix (B, C*9, HW)

// ---------------------------------------------------------------------------
// Kernel 1: partial offsets conv. Each block handles 2 image rows and ONE
// 32-channel split, computing all 18 oc partial sums for its pixels.
// Grid = (128 row-groups, 8 splits) = 1024 blocks -> ~27 warps/SM occupancy.
// x stencil loaded once per channel into registers, reused across 18 ocs.
// Weights staged in smem transposed to ws[c][tap][oc] (broadcast LDS).
// ---------------------------------------------------------------------------
__global__ __launch_bounds__(128) void offsets_part_kernel(
    const float* __restrict__ x, const float* __restrict__ w_off)
{
    __shared__ float ws[8][9][20];   // [c][tap][oc] padded

    const int blk   = blockIdx.x;       // 0..127
    const int split = blockIdx.y;       // 0..7
    const int b     = blk >> 5;         // image
    const int row2  = (blk & 31) * 2;   // first of 2 rows
    const int ho    = row2 + (threadIdx.x >> 6);
    const int wo    = threadIdx.x & 63;

    float acc[18];
#pragma unroll
    for (int o = 0; o < 18; o++) acc[o] = 0.f;

    const float* xb = x + (size_t)b * CIN * HW;
    const int cbase = split * (CIN / NSPLIT);   // 32 channels per split

    for (int c0 = cbase; c0 < cbase + CIN / NSPLIT; c0 += 8) {
        __syncthreads();
        for (int i = threadIdx.x; i < 18 * 8 * 9; i += 128) {
            int oc = i / 72; int rem = i % 72; int c = rem / 9; int tap = rem % 9;
            ws[c][tap][oc] = w_off[(size_t)oc * CIN * 9 + (size_t)(c0 + c) * 9 + tap];
        }
        __syncthreads();
#pragma unroll
        for (int c = 0; c < 8; c++) {
            const float* xc = xb + (size_t)(c0 + c) * HW;
            float xv[9];
#pragma unroll
            for (int ky = 0; ky < 3; ky++) {
                int y = ho + ky - 1;
                bool vy = (y >= 0) && (y < Hdim);
#pragma unroll
                for (int kx = 0; kx < 3; kx++) {
                    int xx = wo + kx - 1;
                    xv[ky * 3 + kx] = (vy && xx >= 0 && xx < Wdim) ? __ldg(xc + y * Wdim + xx) : 0.f;
                }
            }
#pragma unroll
            for (int tap = 0; tap < 9; tap++) {
                float xt = xv[tap];
#pragma unroll
                for (int o = 0; o < 18; o++)
                    acc[o] += xt * ws[c][tap][o];
            }
        }
    }

    const int hw = ho * Wdim + wo;
#pragma unroll
    for (int o = 0; o < 18; o++)
        g_offp[split][((size_t)b * 18 + o) * HW + hw] = acc[o];
}

// ---------------------------------------------------------------------------
// Kernel 2: bilinear gather -> g_val[b][c*9+k][hw].
// Sums the 8 offset partials inline (16 coalesced loads per thread).
// Corner indices/weights computed ONCE, reused over all 256 channels.
// ---------------------------------------------------------------------------
__global__ __launch_bounds__(256) void gather_kernel(const float* __restrict__ x)
{
    int idx = blockIdx.x * blockDim.x + threadIdx.x;
    if (idx >= BATCH * KK * HW) return;
    int hw = idx & 4095;
    int k  = (idx >> 12) % KK;
    int b  = idx / (KK * HW);
    int ho = hw >> 6, wo = hw & 63;
    int ky = k / 3,  kx = k % 3;

    const size_t oy = ((size_t)b * 18 + 2 * k + 0) * HW + hw;
    const size_t ox = ((size_t)b * 18 + 2 * k + 1) * HW + hw;
    float dy = 0.f, dx = 0.f;
#pragma unroll
    for (int s = 0; s < NSPLIT; s++) {
        dy += g_offp[s][oy];
        dx += g_offp[s][ox];
    }

    float py = (float)(ho - 1 + ky) + dy;
    float px = (float)(wo - 1 + kx) + dx;
    float y0f = floorf(py), x0f = floorf(px);
    int   y0 = (int)y0f,    x0 = (int)x0f;
    float wy1 = py - y0f, wx1 = px - x0f;
    float wy0 = 1.f - wy1, wx0 = 1.f - wx1;
    int y1 = y0 + 1, x1 = x0 + 1;

    bool vy0 = (y0 >= 0) & (y0 < Hdim);
    bool vy1 = (y1 >= 0) & (y1 < Hdim);
    bool vx0 = (x0 >= 0) & (x0 < Wdim);
    bool vx1 = (x1 >= 0) & (x1 < Wdim);

    float w00 = (vy0 && vx0) ? wy0 * wx0 : 0.f;
    float w01 = (vy0 && vx1) ? wy0 * wx1 : 0.f;
    float w10 = (vy1 && vx0) ? wy1 * wx0 : 0.f;
    float w11 = (vy1 && vx1) ? wy1 * wx1 : 0.f;

    int y0c = min(max(y0, 0), Hdim - 1), y1c = min(max(y1, 0), Hdim - 1);
    int x0c = min(max(x0, 0), Wdim - 1), x1c = min(max(x1, 0), Wdim - 1);
    int i00 = y0c * Wdim + x0c, i01 = y0c * Wdim + x1c;
    int i10 = y1c * Wdim + x0c, i11 = y1c * Wdim + x1c;

    const float* xb = x + (size_t)b * CIN * HW;
    float* vout = g_val + ((size_t)b * PDIM + k) * HW + hw;   // p = c*9 + k

    for (int c = 0; c < CIN; c++) {
        const float* xc = xb + c * HW;
        float v = w00 * __ldg(xc + i00) + w01 * __ldg(xc + i01)
                + w10 * __ldg(xc + i10) + w11 * __ldg(xc + i11);
        vout[(size_t)c * KK * HW] = v;
    }
}

// ---------------------------------------------------------------------------
// Kernel 3: TF32 tensor-core GEMM  C[b] = A[256,2304] * Bv[b][2304,4096]
// mma.sync.aligned.m16n8k8.row.col.f32.tf32.tf32.f32
// Block tile 128x128, BK=16, 256 threads (8 warps 2x4), warp = 64x32.
// Smem k dim permuted within each 8-group so fragment loads are LDS.64.
// ---------------------------------------------------------------------------
#define BM 128
#define BN 128
#define BK 16
#define KPAD 18   // padded floats per smem row

__device__ __forceinline__ float f2tf32(float f) {
    unsigned r;
    asm("cvt.rna.tf32.f32 %0, %1;" : "=r"(r) : "f"(f));
    return __uint_as_float(r);
}

__device__ __forceinline__ void mma_tf32(float4& d, float2 alo, float2 ahi, float2 bb) {
    asm volatile(
        "mma.sync.aligned.m16n8k8.row.col.f32.tf32.tf32.f32 "
        "{%0,%1,%2,%3}, {%4,%5,%6,%7}, {%8,%9}, {%0,%1,%2,%3};"
        : "+f"(d.x), "+f"(d.y), "+f"(d.z), "+f"(d.w)
        : "r"(__float_as_uint(alo.x)), "r"(__float_as_uint(ahi.x)),
          "r"(__float_as_uint(alo.y)), "r"(__float_as_uint(ahi.y)),
          "r"(__float_as_uint(bb.x)),  "r"(__float_as_uint(bb.y)));
}

__global__ __launch_bounds__(256) void mma_gemm_kernel(
    const float* __restrict__ A, float* __restrict__ C)
{
    __shared__ float As[2][BM][KPAD];
    __shared__ float Bs[2][BN][KPAD];

    const int b  = blockIdx.z;
    const float* Bp = g_val + (size_t)b * PDIM * HW;
    float*       Cp = C     + (size_t)b * COUT * HW;
    const int m0 = blockIdx.y * BM;
    const int n0 = blockIdx.x * BN;

    const int tid  = threadIdx.x;
    const int warp = tid >> 5;
    const int lane = tid & 31;
    const int g = lane >> 2;            // 0..7
    const int t = lane & 3;             // 0..3
    const int wm = (warp >> 2) * 64;    // warp M offset: 0 or 64
    const int wn = (warp & 3) * 32;     // warp N offset: 0..96

    float4 acc[4][4];
#pragma unroll
    for (int i = 0; i < 4; i++)
#pragma unroll
        for (int j = 0; j < 4; j++) acc[i][j] = make_float4(0.f, 0.f, 0.f, 0.f);

    // gmem load mapping
    const int am = tid >> 1;                 // A row within tile, 0..127
    const int aq = (tid & 1) * 2;            // first of 2 quads (k4 index)
    const float* aptr = A + (size_t)(m0 + am) * PDIM + aq * 4;
    const int bk = tid >> 4;                 // B k-row within tile, 0..15
    const int bn = (tid & 15) * 4;           // B n offset, 0..60
    const float* bptr = Bp + (size_t)bk * HW + n0 + bn;

    // physical (permuted) k column for B row bk: pairs {t, t+4} adjacent
    const int bphys = 8 * (bk >> 3) + 2 * (bk & 3) + ((bk >> 2) & 1);

    float4 pa[2], pb[2];

    // prologue: load tile 0
    pa[0] = *(const float4*)(aptr);
    pa[1] = *(const float4*)(aptr + 4);
    pb[0] = *(const float4*)(bptr);
    pb[1] = *(const float4*)(bptr + 64);

    const int nk = PDIM / BK;   // 144
    for (int it = 0; it < nk; it++) {
        const int s = it & 1;

        // commit current tile to smem stage s (tf32-rounded, k-permuted)
#pragma unroll
        for (int j = 0; j < 2; j++) {
            const int q = aq + j;
            const int base = 8 * (q >> 1) + (q & 1);
            float4 v = pa[j];
            As[s][am][base + 0] = f2tf32(v.x);
            As[s][am][base + 2] = f2tf32(v.y);
            As[s][am][base + 4] = f2tf32(v.z);
            As[s][am][base + 6] = f2tf32(v.w);
        }
#pragma unroll
        for (int j = 0; j < 2; j++) {
            const int n = bn + 64 * j;
            float4 v = pb[j];
            Bs[s][n + 0][bphys] = f2tf32(v.x);
            Bs[s][n + 1][bphys] = f2tf32(v.y);
            Bs[s][n + 2][bphys] = f2tf32(v.z);
            Bs[s][n + 3][bphys] = f2tf32(v.w);
        }
        __syncthreads();

        // prefetch next tile while computing
        if (it + 1 < nk) {
            const int kt = (it + 1) * BK;
            pa[0] = *(const float4*)(aptr + kt);
            pa[1] = *(const float4*)(aptr + kt + 4);
            pb[0] = *(const float4*)(bptr + (size_t)kt * HW);
            pb[1] = *(const float4*)(bptr + (size_t)kt * HW + 64);
        }

        // compute 2 k8-steps from stage s
#pragma unroll
        for (int k8 = 0; k8 < 2; k8++) {
            const int cb = k8 * 8 + 2 * t;
            float2 alo[4], ahi[4], bb[4];
#pragma unroll
            for (int mt = 0; mt < 4; mt++) {
                alo[mt] = *(const float2*)&As[s][wm + mt * 16 + g][cb];
                ahi[mt] = *(const float2*)&As[s][wm + mt * 16 + g + 8][cb];
            }
#pragma unroll
            for (int nt = 0; nt < 4; nt++)
                bb[nt] = *(const float2*)&Bs[s][wn + nt * 8 + g][cb];
#pragma unroll
            for (int mt = 0; mt < 4; mt++)
#pragma unroll
                for (int nt = 0; nt < 4; nt++)
                    mma_tf32(acc[mt][nt], alo[mt], ahi[mt], bb[nt]);
        }
        __syncthreads();
    }

    // epilogue: D fragment -> gmem (c0,c1 at row g col 2t; c2,c3 at row g+8)
#pragma unroll
    for (int mt = 0; mt < 4; mt++) {
#pragma unroll
        for (int nt = 0; nt < 4; nt++) {
            const int row = m0 + wm + mt * 16 + g;
            const int col = n0 + wn + nt * 8 + 2 * t;
            float4 d = acc[mt][nt];
            *(float2*)(Cp + (size_t)row * HW + col)       = make_float2(d.x, d.y);
            *(float2*)(Cp + (size_t)(row + 8) * HW + col) = make_float2(d.z, d.w);
        }
    }
}

// ---------------------------------------------------------------------------
extern "C" void kernel_launch(void* const* d_in, const int* in_sizes, int n_in,
                              void* d_out, int out_size)
{
    const float* x     = (const float*)d_in[0];   // (4,256,64,64)
    const float* w_def = (const float*)d_in[1];   // (256,256,3,3)
    const float* w_off = (const float*)d_in[2];   // (18,256,3,3)
    float* out = (float*)d_out;                   // (4,256,64,64)

    offsets_part_kernel<<<dim3(BATCH * 32, NSPLIT), 128>>>(x, w_off);
    gather_kernel<<<(BATCH * KK * HW + 255) / 256, 256>>>(x);
    mma_gemm_kernel<<<dim3(HW / BN, COUT / BM, BATCH), 256>>>(w_def, out);
}